// round 1
// baseline (speedup 1.0000x reference)
#include <cuda_runtime.h>
#include <math.h>

#define B_    64
#define S_    1024
#define D_    800
#define MS_   16
#define T_    32
#define H_    200
#define NS_   12
#define NSPAN (B_*MS_)        // 1024
#define MROWS (NSPAN*T_)      // 32768
#define KDIM  D_              // 800
#define G4H   (4*H_)          // 800
#define NCOLS (2*G4H)         // 1600 (fwd gates | bwd gates)
#define PSPAN 8

// -------- scratch (static device allocations; no runtime alloc allowed) -----
__device__ float  g_Z[2][(size_t)MROWS * G4H];   // 2 x 104.9 MB: gate pre-activations (x@Wih^T + bias)
__device__ float  g_WT[(size_t)KDIM * NCOLS];    // transposed input weights [k][j]
__device__ float4 g_Wp[2][H_ * H_];              // packed recurrent weights [dir][k*H + u] = (Wi,Wf,Wg,Wo)
__device__ float  g_biasC[NCOLS];                // bih + bhh, both dirs
__device__ float  g_feats[(size_t)NSPAN * 2 * H_];

// ---------------------------------------------------------------------------
// Pack: transpose Wih (both dirs) to [k][j], gate-pack Whh to float4[k][u],
// combine biases. Cheap, runs every launch (deterministic).
// ---------------------------------------------------------------------------
__global__ void pack_kernel(const float* __restrict__ Wih_f, const float* __restrict__ Whh_f,
                            const float* __restrict__ bih_f, const float* __restrict__ bhh_f,
                            const float* __restrict__ Wih_b, const float* __restrict__ Whh_b,
                            const float* __restrict__ bih_b, const float* __restrict__ bhh_b) {
    int stride = gridDim.x * blockDim.x;
    int tid0   = blockIdx.x * blockDim.x + threadIdx.x;

    for (int idx = tid0; idx < KDIM * NCOLS; idx += stride) {
        int k = idx / NCOLS, j = idx % NCOLS;
        g_WT[idx] = (j < G4H) ? Wih_f[(size_t)j * D_ + k]
                              : Wih_b[(size_t)(j - G4H) * D_ + k];
    }
    for (int idx = tid0; idx < 2 * H_ * H_; idx += stride) {
        int dir = idx / (H_ * H_);
        int rem = idx % (H_ * H_);
        int k = rem / H_, u = rem % H_;
        const float* Whh = dir ? Whh_b : Whh_f;
        float4 v;
        v.x = Whh[(size_t)(0 * H_ + u) * H_ + k];
        v.y = Whh[(size_t)(1 * H_ + u) * H_ + k];
        v.z = Whh[(size_t)(2 * H_ + u) * H_ + k];
        v.w = Whh[(size_t)(3 * H_ + u) * H_ + k];
        g_Wp[dir][k * H_ + u] = v;
    }
    for (int idx = tid0; idx < NCOLS; idx += stride) {
        int dir = idx / G4H, jj = idx % G4H;
        g_biasC[idx] = dir ? (bih_b[jj] + bhh_b[jj]) : (bih_f[jj] + bhh_f[jj]);
    }
}

// ---------------------------------------------------------------------------
// Gathered SGEMM: Z[r, j] = x_gather[r, :] @ WT[:, j] + biasC[j]
// r = span*32 + t, gathered from hidden_layers via span_starts.
// 128x128x16 tile, 256 threads, 8x8 microtile.
// ---------------------------------------------------------------------------
__global__ __launch_bounds__(256) void gemm_kernel(const float* __restrict__ hidden,
                                                   const int*   __restrict__ starts) {
    __shared__ float As[16][128];
    __shared__ float Bs[16][128];
    __shared__ int   rowOff[128];

    int tid = threadIdx.x;
    int n0  = blockIdx.x * 128;
    int m0  = blockIdx.y * 128;

    if (tid < 128) {
        int r   = m0 + tid;
        int sp  = r >> 5;          // span index
        int t   = r & 31;
        int b   = sp >> 4, mm = sp & 15;
        int src = starts[b * MS_ + mm] + t;
        src = min(max(src, 0), S_ - 1);
        rowOff[tid] = (b * S_ + src) * D_;
    }

    float acc[8][8];
#pragma unroll
    for (int i = 0; i < 8; i++)
#pragma unroll
        for (int j = 0; j < 8; j++) acc[i][j] = 0.f;

    int tx = tid & 15, ty = tid >> 4;

    for (int k0 = 0; k0 < KDIM; k0 += 16) {
        __syncthreads();   // rowOff ready (first iter) / prev compute done
#pragma unroll
        for (int i = 0; i < 2; i++) {
            int idx = tid + i * 256;
            int m = idx >> 2, kq = idx & 3;
            float4 v = *reinterpret_cast<const float4*>(&hidden[rowOff[m] + k0 + kq * 4]);
            As[kq * 4 + 0][m] = v.x;
            As[kq * 4 + 1][m] = v.y;
            As[kq * 4 + 2][m] = v.z;
            As[kq * 4 + 3][m] = v.w;
        }
#pragma unroll
        for (int i = 0; i < 2; i++) {
            int idx = tid + i * 256;
            int k = idx >> 5, nq = idx & 31;
            int col = n0 + nq * 4;
            float4 v = make_float4(0.f, 0.f, 0.f, 0.f);
            if (col < NCOLS)
                v = *reinterpret_cast<const float4*>(&g_WT[(size_t)(k0 + k) * NCOLS + col]);
            *reinterpret_cast<float4*>(&Bs[k][nq * 4]) = v;
        }
        __syncthreads();
#pragma unroll
        for (int k = 0; k < 16; k++) {
            float a[8], b[8];
            *reinterpret_cast<float4*>(&a[0]) = *reinterpret_cast<const float4*>(&As[k][ty * 8]);
            *reinterpret_cast<float4*>(&a[4]) = *reinterpret_cast<const float4*>(&As[k][ty * 8 + 4]);
            *reinterpret_cast<float4*>(&b[0]) = *reinterpret_cast<const float4*>(&Bs[k][tx * 8]);
            *reinterpret_cast<float4*>(&b[4]) = *reinterpret_cast<const float4*>(&Bs[k][tx * 8 + 4]);
#pragma unroll
            for (int i = 0; i < 8; i++)
#pragma unroll
                for (int j = 0; j < 8; j++) acc[i][j] += a[i] * b[j];
        }
    }

    int rowb = m0 + ty * 8;
    int colb = n0 + tx * 8;
#pragma unroll
    for (int i = 0; i < 8; i++) {
        int row = rowb + i;
#pragma unroll
        for (int j = 0; j < 8; j++) {
            int col = colb + j;
            if (col < NCOLS) {
                float v = acc[i][j] + g_biasC[col];
                if (col < G4H) g_Z[0][(size_t)row * G4H + col]          = v;
                else           g_Z[1][(size_t)row * G4H + (col - G4H)] = v;
            }
        }
    }
}

// ---------------------------------------------------------------------------
// Recurrence: thread u owns hidden unit u; c and masked-sum feature live in
// registers across all steps, h in shared. One CTA handles PSPAN spans for
// one direction. Backward = forward over t = L-1..0 (masked-scan equivalence).
// ---------------------------------------------------------------------------
__global__ __launch_bounds__(224) void lstm_kernel(const int* __restrict__ span_lens) {
    __shared__ float h_sh[PSPAN][H_];
    __shared__ int   len_sh[PSPAN];
    __shared__ int   maxL_sh;

    int tid = threadIdx.x;
    int dir = blockIdx.y;
    int n0  = blockIdx.x * PSPAN;

    if (tid < PSPAN) len_sh[tid] = span_lens[n0 + tid];
    if (tid < H_) {
#pragma unroll
        for (int p = 0; p < PSPAN; p++) h_sh[p][tid] = 0.f;
    }
    __syncthreads();
    if (tid == 0) {
        int m = 0;
#pragma unroll
        for (int p = 0; p < PSPAN; p++) m = max(m, len_sh[p]);
        maxL_sh = m;
    }
    __syncthreads();
    int maxL = maxL_sh;

    int u = tid;
    float c[PSPAN], feat[PSPAN];
#pragma unroll
    for (int p = 0; p < PSPAN; p++) { c[p] = 0.f; feat[p] = 0.f; }

    const float*  Zd = g_Z[dir];
    const float4* Wp = g_Wp[dir];

    for (int s = 0; s < maxL; s++) {
        float a0[PSPAN], a1[PSPAN], a2[PSPAN], a3[PSPAN];
        if (u < H_) {
#pragma unroll
            for (int p = 0; p < PSPAN; p++) {
                int L = len_sh[p];
                int t = dir ? (L - 1 - s) : s;
                if (s >= L) t = 0;   // dummy valid address; result discarded
                const float* z = Zd + ((size_t)(n0 + p) * T_ + t) * G4H;
                a0[p] = z[u];
                a1[p] = z[H_ + u];
                a2[p] = z[2 * H_ + u];
                a3[p] = z[3 * H_ + u];
            }
#pragma unroll 2
            for (int k = 0; k < H_; k++) {
                float4 w = Wp[k * H_ + u];
#pragma unroll
                for (int p = 0; p < PSPAN; p++) {
                    float hk = h_sh[p][k];
                    a0[p] += w.x * hk;
                    a1[p] += w.y * hk;
                    a2[p] += w.z * hk;
                    a3[p] += w.w * hk;
                }
            }
        }
        __syncthreads();   // everyone done reading h_sh
        if (u < H_) {
#pragma unroll
            for (int p = 0; p < PSPAN; p++) {
                if (s < len_sh[p]) {
                    float ig = 1.f / (1.f + __expf(-a0[p]));
                    float fg = 1.f / (1.f + __expf(-a1[p]));
                    float gg = tanhf(a2[p]);
                    float og = 1.f / (1.f + __expf(-a3[p]));
                    float cn = fg * c[p] + ig * gg;
                    c[p] = cn;
                    float hn = og * tanhf(cn);
                    h_sh[p][u] = hn;
                    feat[p] += hn;   // = sum_t h_t * m_t
                }
            }
        }
        __syncthreads();   // h writes visible before next step's reads
    }

    if (u < H_) {
#pragma unroll
        for (int p = 0; p < PSPAN; p++)
            g_feats[(size_t)(n0 + p) * (2 * H_) + dir * H_ + u] = feat[p];
    }
}

// ---------------------------------------------------------------------------
// logits[b,m,ns] = (feats[n] . slot_embs[:,ns]) * slot_mask[n]
// ---------------------------------------------------------------------------
__global__ void logits_kernel(const float* __restrict__ slot_embs,
                              const float* __restrict__ slot_mask,
                              float* __restrict__ out) {
    int idx = blockIdx.x * blockDim.x + threadIdx.x;
    if (idx >= NSPAN * NS_) return;
    int n = idx / NS_, ns = idx % NS_;
    const float* f = &g_feats[(size_t)n * (2 * H_)];
    float acc = 0.f;
#pragma unroll 8
    for (int h = 0; h < 2 * H_; h++) acc += f[h] * slot_embs[h * NS_ + ns];
    out[idx] = acc * slot_mask[n];
}

// ---------------------------------------------------------------------------
extern "C" void kernel_launch(void* const* d_in, const int* in_sizes, int n_in,
                              void* d_out, int out_size) {
    const float* hidden    = (const float*)d_in[0];
    const float* Wih_f     = (const float*)d_in[1];
    const float* Whh_f     = (const float*)d_in[2];
    const float* bih_f     = (const float*)d_in[3];
    const float* bhh_f     = (const float*)d_in[4];
    const float* Wih_b     = (const float*)d_in[5];
    const float* Whh_b     = (const float*)d_in[6];
    const float* bih_b     = (const float*)d_in[7];
    const float* bhh_b     = (const float*)d_in[8];
    const float* slot_embs = (const float*)d_in[9];
    const int*   starts    = (const int*)d_in[10];
    const int*   lens      = (const int*)d_in[11];
    const float* slot_mask = (const float*)d_in[12];
    float* out = (float*)d_out;

    pack_kernel<<<1024, 256>>>(Wih_f, Whh_f, bih_f, bhh_f,
                               Wih_b, Whh_b, bih_b, bhh_b);

    dim3 ggrid((NCOLS + 127) / 128, MROWS / 128);   // 13 x 256
    gemm_kernel<<<ggrid, 256>>>(hidden, starts);

    dim3 lgrid(NSPAN / PSPAN, 2);                   // 128 x 2
    lstm_kernel<<<lgrid, 224>>>(lens);

    logits_kernel<<<(NSPAN * NS_ + 255) / 256, 256>>>(slot_embs, slot_mask, out);
}

// round 2
// speedup vs baseline: 2.0526x; 2.0526x over previous
#include <cuda_runtime.h>
#include <math.h>

#define B_    64
#define S_    1024
#define D_    800
#define MS_   16
#define T_    32
#define H_    200
#define NS_   12
#define NSPAN (B_*MS_)        // 1024
#define MROWS (NSPAN*T_)      // 32768
#define KDIM  D_              // 800
#define G4H   (4*H_)          // 800
#define NCOLS (2*G4H)         // 1600 (fwd gates | bwd gates)
#define PSPAN 8
#define KC    32
#define PADLD 136             // row pitch: (k*136) % 32 == 8k -> conflict-free frag loads

// -------- scratch (static device allocations; no runtime alloc allowed) -----
__device__ float  g_Z[2][(size_t)MROWS * G4H];   // gate pre-activations
__device__ float  g_WT[(size_t)KDIM * NCOLS];    // transposed input weights [k][j]
__device__ float4 g_Wp[2][H_ * H_];              // packed recurrent weights [dir][k*H+u]
__device__ float  g_biasC[NCOLS];
__device__ float  g_feats[(size_t)NSPAN * 2 * H_];
__device__ int    g_rows[MROWS];                 // compacted valid-row list
__device__ int    g_order[NSPAN];                // spans sorted by length
__device__ int    g_cnt;                         // number of valid rows

// ---------------------------------------------------------------------------
// Pack weights
// ---------------------------------------------------------------------------
__global__ void pack_kernel(const float* __restrict__ Wih_f, const float* __restrict__ Whh_f,
                            const float* __restrict__ bih_f, const float* __restrict__ bhh_f,
                            const float* __restrict__ Wih_b, const float* __restrict__ Whh_b,
                            const float* __restrict__ bih_b, const float* __restrict__ bhh_b) {
    int stride = gridDim.x * blockDim.x;
    int tid0   = blockIdx.x * blockDim.x + threadIdx.x;

    for (int idx = tid0; idx < KDIM * NCOLS; idx += stride) {
        int k = idx / NCOLS, j = idx % NCOLS;
        g_WT[idx] = (j < G4H) ? Wih_f[(size_t)j * D_ + k]
                              : Wih_b[(size_t)(j - G4H) * D_ + k];
    }
    for (int idx = tid0; idx < 2 * H_ * H_; idx += stride) {
        int dir = idx / (H_ * H_);
        int rem = idx % (H_ * H_);
        int k = rem / H_, u = rem % H_;
        const float* Whh = dir ? Whh_b : Whh_f;
        float4 v;
        v.x = Whh[(size_t)(0 * H_ + u) * H_ + k];
        v.y = Whh[(size_t)(1 * H_ + u) * H_ + k];
        v.z = Whh[(size_t)(2 * H_ + u) * H_ + k];
        v.w = Whh[(size_t)(3 * H_ + u) * H_ + k];
        g_Wp[dir][k * H_ + u] = v;
    }
    for (int idx = tid0; idx < NCOLS; idx += stride) {
        int dir = idx / G4H, jj = idx % G4H;
        g_biasC[idx] = dir ? (bih_b[jj] + bhh_b[jj]) : (bih_f[jj] + bhh_f[jj]);
    }
}

// ---------------------------------------------------------------------------
// Prefix-scan of span lengths -> compacted valid-row list (row = span*32+t, t<len)
// ---------------------------------------------------------------------------
__global__ void scan_kernel(const int* __restrict__ lens) {
    __shared__ int s[NSPAN];
    int tid = threadIdx.x;
    int l = lens[tid];
    l = min(max(l, 0), T_);
    s[tid] = l;
    __syncthreads();
    for (int d = 1; d < NSPAN; d <<= 1) {
        int v = (tid >= d) ? s[tid - d] : 0;
        __syncthreads();
        s[tid] += v;
        __syncthreads();
    }
    int off = s[tid] - l;
    for (int t = 0; t < l; t++) g_rows[off + t] = tid * T_ + t;
    if (tid == NSPAN - 1) g_cnt = s[NSPAN - 1];
}

// ---------------------------------------------------------------------------
// Deterministic counting sort of spans by length (ascending, stable)
// ---------------------------------------------------------------------------
__global__ void sort_kernel(const int* __restrict__ lens) {
    __shared__ int cnt[T_ + 1];
    __shared__ int start[T_ + 1];
    int tid = threadIdx.x;
    if (tid <= T_) cnt[tid] = 0;
    __syncthreads();
    for (int i = tid; i < NSPAN; i += blockDim.x) {
        int l = min(max(lens[i], 0), T_);
        atomicAdd(&cnt[l], 1);
    }
    __syncthreads();
    if (tid == 0) {
        int acc = 0;
        for (int l = 0; l <= T_; l++) { start[l] = acc; acc += cnt[l]; }
    }
    __syncthreads();
    if (tid <= T_) {
        int pos = start[tid];
        for (int i = 0; i < NSPAN; i++) {
            int l = min(max(lens[i], 0), T_);
            if (l == tid) g_order[pos++] = i;
        }
    }
}

// ---------------------------------------------------------------------------
// Tensor-core gathered GEMM, tf32 3-pass (Ah*Bh + Ah*Bl + Al*Bh ~ fp32 precision)
// Tile 128x128xKC, 256 threads (8 warps as 2x4), warp tile 64x32, mma m16n8k8.
// Only computes valid (compacted) rows; writes Z at original row indices.
// ---------------------------------------------------------------------------
#define MMA_TF32(d, a, b)                                                      \
    asm volatile("mma.sync.aligned.m16n8k8.row.col.f32.tf32.tf32.f32 "          \
                 "{%0,%1,%2,%3}, {%4,%5,%6,%7}, {%8,%9}, {%0,%1,%2,%3};"        \
                 : "+f"(d[0]), "+f"(d[1]), "+f"(d[2]), "+f"(d[3])               \
                 : "r"(a[0]), "r"(a[1]), "r"(a[2]), "r"(a[3]),                  \
                   "r"(b[0]), "r"(b[1]));

__device__ __forceinline__ void tf32_split(float x, unsigned& hi, unsigned& lo) {
    asm("cvt.rna.tf32.f32 %0, %1;" : "=r"(hi) : "f"(x));
    float r = x - __uint_as_float(hi);
    asm("cvt.rna.tf32.f32 %0, %1;" : "=r"(lo) : "f"(r));
}

extern __shared__ float smem_dyn[];

__global__ __launch_bounds__(256, 1) void gemm_tc(const float* __restrict__ hidden,
                                                  const int*   __restrict__ starts) {
    const int cnt = g_cnt;
    const int m0  = blockIdx.y * 128;
    if (m0 >= cnt) return;
    const int n0  = blockIdx.x * 128;

    float* As_hi = smem_dyn;
    float* As_lo = As_hi + KC * PADLD;
    float* Bs_hi = As_lo + KC * PADLD;
    float* Bs_lo = Bs_hi + KC * PADLD;
    __shared__ int rowOff[128];
    __shared__ int rowIdx[128];

    int tid = threadIdx.x;
    if (tid < 128) {
        int m = m0 + tid;
        int r = (m < cnt) ? g_rows[m] : 0;
        rowIdx[tid] = r;
        int sp = r >> 5, t = r & 31;
        int b = sp >> 4, mm = sp & 15;
        int src = starts[b * MS_ + mm] + t;
        src = min(max(src, 0), S_ - 1);
        rowOff[tid] = (b * S_ + src) * D_;
    }

    float acc[16][4];
#pragma unroll
    for (int i = 0; i < 16; i++)
#pragma unroll
        for (int q = 0; q < 4; q++) acc[i][q] = 0.f;

    int lane = tid & 31, wid = tid >> 5;
    int wm = wid >> 2, wn = wid & 3;       // warp grid 2 (M) x 4 (N)
    int g = lane >> 2, tg = lane & 3;      // groupID, threadID_in_group

    for (int k0 = 0; k0 < KDIM; k0 += KC) {
        __syncthreads();
        // ---- load + split A (gathered rows): 128 x 32 ----
#pragma unroll
        for (int i = 0; i < 4; i++) {
            int id = tid + i * 256;
            int m = id & 127, kq = id >> 7;  // kq 0..7
            float4 v = *reinterpret_cast<const float4*>(&hidden[rowOff[m] + k0 + kq * 4]);
            float xs[4] = {v.x, v.y, v.z, v.w};
#pragma unroll
            for (int j = 0; j < 4; j++) {
                unsigned hi, lo;
                tf32_split(xs[j], hi, lo);
                As_hi[(kq * 4 + j) * PADLD + m] = __uint_as_float(hi);
                As_lo[(kq * 4 + j) * PADLD + m] = __uint_as_float(lo);
            }
        }
        // ---- load + split B: 32 x 128 ----
#pragma unroll
        for (int i = 0; i < 4; i++) {
            int id = tid + i * 256;
            int n4 = id & 31, k = id >> 5;
            int col = n0 + n4 * 4;
            float4 v = make_float4(0.f, 0.f, 0.f, 0.f);
            if (col < NCOLS)
                v = *reinterpret_cast<const float4*>(&g_WT[(size_t)(k0 + k) * NCOLS + col]);
            float xs[4] = {v.x, v.y, v.z, v.w};
#pragma unroll
            for (int j = 0; j < 4; j++) {
                unsigned hi, lo;
                tf32_split(xs[j], hi, lo);
                Bs_hi[k * PADLD + n4 * 4 + j] = __uint_as_float(hi);
                Bs_lo[k * PADLD + n4 * 4 + j] = __uint_as_float(lo);
            }
        }
        __syncthreads();

#pragma unroll
        for (int ks = 0; ks < 4; ks++) {
            int kk = ks * 8;
            unsigned ah[4][4], al[4][4];
#pragma unroll
            for (int mt = 0; mt < 4; mt++) {
                int r0 = wm * 64 + mt * 16 + g;
                ah[mt][0] = __float_as_uint(As_hi[(kk + tg) * PADLD + r0]);
                ah[mt][1] = __float_as_uint(As_hi[(kk + tg) * PADLD + r0 + 8]);
                ah[mt][2] = __float_as_uint(As_hi[(kk + tg + 4) * PADLD + r0]);
                ah[mt][3] = __float_as_uint(As_hi[(kk + tg + 4) * PADLD + r0 + 8]);
                al[mt][0] = __float_as_uint(As_lo[(kk + tg) * PADLD + r0]);
                al[mt][1] = __float_as_uint(As_lo[(kk + tg) * PADLD + r0 + 8]);
                al[mt][2] = __float_as_uint(As_lo[(kk + tg + 4) * PADLD + r0]);
                al[mt][3] = __float_as_uint(As_lo[(kk + tg + 4) * PADLD + r0 + 8]);
            }
            unsigned bh[4][2], bl[4][2];
#pragma unroll
            for (int nt = 0; nt < 4; nt++) {
                int c = wn * 32 + nt * 8 + g;
                bh[nt][0] = __float_as_uint(Bs_hi[(kk + tg) * PADLD + c]);
                bh[nt][1] = __float_as_uint(Bs_hi[(kk + tg + 4) * PADLD + c]);
                bl[nt][0] = __float_as_uint(Bs_lo[(kk + tg) * PADLD + c]);
                bl[nt][1] = __float_as_uint(Bs_lo[(kk + tg + 4) * PADLD + c]);
            }
#pragma unroll
            for (int mt = 0; mt < 4; mt++)
#pragma unroll
                for (int nt = 0; nt < 4; nt++) {
                    MMA_TF32(acc[mt * 4 + nt], ah[mt], bh[nt]);
                    MMA_TF32(acc[mt * 4 + nt], ah[mt], bl[nt]);
                    MMA_TF32(acc[mt * 4 + nt], al[mt], bh[nt]);
                }
        }
    }

    // ---- epilogue: bias + scatter-store to Z at original row ids ----
#pragma unroll
    for (int mt = 0; mt < 4; mt++) {
        int lr0 = wm * 64 + mt * 16 + g;
#pragma unroll
        for (int nt = 0; nt < 4; nt++) {
            int c0 = n0 + wn * 32 + nt * 8 + tg * 2;
            float* a = acc[mt * 4 + nt];
#pragma unroll
            for (int q = 0; q < 4; q++) {
                int lr = lr0 + ((q >= 2) ? 8 : 0);
                int c  = c0 + (q & 1);
                if (m0 + lr < cnt && c < NCOLS) {
                    float v = a[q] + g_biasC[c];
                    int rid = rowIdx[lr];
                    if (c < G4H) g_Z[0][(size_t)rid * G4H + c]          = v;
                    else         g_Z[1][(size_t)rid * G4H + (c - G4H)] = v;
                }
            }
        }
    }
}

// ---------------------------------------------------------------------------
// Recurrence: thread u owns hidden unit u; spans grouped by sorted length.
// ---------------------------------------------------------------------------
__global__ __launch_bounds__(224) void lstm_kernel(const int* __restrict__ span_lens) {
    __shared__ float h_sh[PSPAN][H_];
    __shared__ int   len_sh[PSPAN];
    __shared__ int   sp_sh[PSPAN];
    __shared__ int   maxL_sh;

    int tid = threadIdx.x;
    int dir = blockIdx.y;
    int n0  = blockIdx.x * PSPAN;

    if (tid < PSPAN) {
        int sp = g_order[n0 + tid];
        sp_sh[tid]  = sp;
        len_sh[tid] = span_lens[sp];
    }
    if (tid < H_) {
#pragma unroll
        for (int p = 0; p < PSPAN; p++) h_sh[p][tid] = 0.f;
    }
    __syncthreads();
    if (tid == 0) {
        int m = 0;
#pragma unroll
        for (int p = 0; p < PSPAN; p++) m = max(m, len_sh[p]);
        maxL_sh = m;
    }
    __syncthreads();
    int maxL = maxL_sh;

    int u = tid;
    float c[PSPAN], feat[PSPAN];
#pragma unroll
    for (int p = 0; p < PSPAN; p++) { c[p] = 0.f; feat[p] = 0.f; }

    const float*  Zd = g_Z[dir];
    const float4* Wp = g_Wp[dir];

    for (int s = 0; s < maxL; s++) {
        float a0[PSPAN], a1[PSPAN], a2[PSPAN], a3[PSPAN];
        if (u < H_) {
#pragma unroll
            for (int p = 0; p < PSPAN; p++) {
                int L = len_sh[p];
                int t = dir ? (L - 1 - s) : s;
                if (s >= L) t = 0;
                const float* z = Zd + ((size_t)sp_sh[p] * T_ + t) * G4H;
                a0[p] = z[u];
                a1[p] = z[H_ + u];
                a2[p] = z[2 * H_ + u];
                a3[p] = z[3 * H_ + u];
            }
#pragma unroll 2
            for (int k = 0; k < H_; k++) {
                float4 w = Wp[k * H_ + u];
#pragma unroll
                for (int p = 0; p < PSPAN; p++) {
                    float hk = h_sh[p][k];
                    a0[p] += w.x * hk;
                    a1[p] += w.y * hk;
                    a2[p] += w.z * hk;
                    a3[p] += w.w * hk;
                }
            }
        }
        __syncthreads();
        if (u < H_) {
#pragma unroll
            for (int p = 0; p < PSPAN; p++) {
                if (s < len_sh[p]) {
                    float ig = 1.f / (1.f + __expf(-a0[p]));
                    float fg = 1.f / (1.f + __expf(-a1[p]));
                    float gg = tanhf(a2[p]);
                    float og = 1.f / (1.f + __expf(-a3[p]));
                    float cn = fg * c[p] + ig * gg;
                    c[p] = cn;
                    float hn = og * tanhf(cn);
                    h_sh[p][u] = hn;
                    feat[p] += hn;
                }
            }
        }
        __syncthreads();
    }

    if (u < H_) {
#pragma unroll
        for (int p = 0; p < PSPAN; p++)
            g_feats[(size_t)sp_sh[p] * (2 * H_) + dir * H_ + u] = feat[p];
    }
}

// ---------------------------------------------------------------------------
// logits: 16 spans x 12 slots per block, feats + slot_embs staged in smem.
// ---------------------------------------------------------------------------
__global__ __launch_bounds__(192) void logits_kernel(const float* __restrict__ slot_embs,
                                                     const float* __restrict__ slot_mask,
                                                     float* __restrict__ out) {
    __shared__ float f_sm[16][2 * H_];
    __shared__ float se_sm[2 * H_ * NS_];

    int tid = threadIdx.x;
    int n0  = blockIdx.x * 16;

    for (int i = tid; i < 2 * H_ * NS_; i += blockDim.x) se_sm[i] = slot_embs[i];
    for (int i = tid; i < 16 * 2 * H_; i += blockDim.x) {
        int sp = i / (2 * H_), h = i % (2 * H_);
        f_sm[sp][h] = g_feats[(size_t)(n0 + sp) * (2 * H_) + h];
    }
    __syncthreads();

    int sp = tid / NS_, ns = tid % NS_;
    float acc = 0.f;
#pragma unroll 8
    for (int h = 0; h < 2 * H_; h++) acc += f_sm[sp][h] * se_sm[h * NS_ + ns];
    out[(n0 + sp) * NS_ + ns] = acc * slot_mask[n0 + sp];
}

// ---------------------------------------------------------------------------
extern "C" void kernel_launch(void* const* d_in, const int* in_sizes, int n_in,
                              void* d_out, int out_size) {
    const float* hidden    = (const float*)d_in[0];
    const float* Wih_f     = (const float*)d_in[1];
    const float* Whh_f     = (const float*)d_in[2];
    const float* bih_f     = (const float*)d_in[3];
    const float* bhh_f     = (const float*)d_in[4];
    const float* Wih_b     = (const float*)d_in[5];
    const float* Whh_b     = (const float*)d_in[6];
    const float* bih_b     = (const float*)d_in[7];
    const float* bhh_b     = (const float*)d_in[8];
    const float* slot_embs = (const float*)d_in[9];
    const int*   starts    = (const int*)d_in[10];
    const int*   lens      = (const int*)d_in[11];
    const float* slot_mask = (const float*)d_in[12];
    float* out = (float*)d_out;

    const int gemm_smem = 4 * KC * PADLD * (int)sizeof(float);   // 69632 B
    cudaFuncSetAttribute(gemm_tc, cudaFuncAttributeMaxDynamicSharedMemorySize, gemm_smem);

    pack_kernel<<<1024, 256>>>(Wih_f, Whh_f, bih_f, bhh_f,
                               Wih_b, Whh_b, bih_b, bhh_b);
    scan_kernel<<<1, NSPAN>>>(lens);
    sort_kernel<<<1, 256>>>(lens);

    dim3 ggrid((NCOLS + 127) / 128, MROWS / 128);   // 13 x 256 (tiles past count exit)
    gemm_tc<<<ggrid, 256, gemm_smem>>>(hidden, starts);

    dim3 lgrid(NSPAN / PSPAN, 2);                   // 128 x 2
    lstm_kernel<<<lgrid, 224>>>(lens);

    logits_kernel<<<NSPAN / 16, 192>>>(slot_embs, slot_mask, out);
}

// round 3
// speedup vs baseline: 2.6982x; 1.3145x over previous
#include <cuda_runtime.h>
#include <math.h>

#define B_    64
#define S_    1024
#define D_    800
#define MS_   16
#define T_    32
#define H_    200
#define NS_   12
#define NSPAN (B_*MS_)        // 1024
#define MROWS (NSPAN*T_)      // 32768
#define KDIM  D_              // 800
#define G4H   (4*H_)          // 800
#define NCOLS (2*G4H)         // 1600
#define NCPAD 1664            // padded so last 128-wide tile stays in-bounds
#define PSPAN 8
#define KC    32
#define APITCH 36             // A smem pitch (floats): bank = (4g+tg)%32 distinct
#define BPITCH 136            // B smem pitch (floats): bank = (8tg+g)%32 distinct

// -------- scratch (static device arrays; no runtime alloc) ------------------
__device__ float  g_Z[2][(size_t)MROWS * G4H];       // gate pre-activations
__device__ float  g_Ahi[(size_t)MROWS * KDIM];       // compacted gathered A, tf32-hi
__device__ float  g_Alo[(size_t)MROWS * KDIM];       // tf32-lo residual
__device__ float  g_Bhi[(size_t)KDIM * NCPAD];       // W^T split hi
__device__ float  g_Blo[(size_t)KDIM * NCPAD];       // W^T split lo
__device__ float4 g_Wp[2][H_ * H_];                  // recurrent weights [dir][k*H+u]
__device__ float  g_biasC[NCOLS];
__device__ float  g_feats[(size_t)NSPAN * 2 * H_];
__device__ int    g_rows[MROWS];                     // compacted valid-row list
__device__ int    g_order[NSPAN];                    // spans sorted by length (asc)
__device__ int    g_cnt;

__device__ __forceinline__ void tf32_split(float x, unsigned& hi, unsigned& lo) {
    asm("cvt.rna.tf32.f32 %0, %1;" : "=r"(hi) : "f"(x));
    float r = x - __uint_as_float(hi);
    asm("cvt.rna.tf32.f32 %0, %1;" : "=r"(lo) : "f"(r));
}

// ---------------------------------------------------------------------------
// Pack: split B=[k][j] (transposed Wih, both dirs) to hi/lo, gate-pack Whh,
// combine biases.
// ---------------------------------------------------------------------------
__global__ void pack_kernel(const float* __restrict__ Wih_f, const float* __restrict__ Whh_f,
                            const float* __restrict__ bih_f, const float* __restrict__ bhh_f,
                            const float* __restrict__ Wih_b, const float* __restrict__ Whh_b,
                            const float* __restrict__ bih_b, const float* __restrict__ bhh_b) {
    int stride = gridDim.x * blockDim.x;
    int tid0   = blockIdx.x * blockDim.x + threadIdx.x;

    for (int idx = tid0; idx < KDIM * NCOLS; idx += stride) {
        int k = idx / NCOLS, j = idx % NCOLS;
        float v = (j < G4H) ? Wih_f[(size_t)j * D_ + k]
                            : Wih_b[(size_t)(j - G4H) * D_ + k];
        unsigned hi, lo;
        tf32_split(v, hi, lo);
        g_Bhi[(size_t)k * NCPAD + j] = __uint_as_float(hi);
        g_Blo[(size_t)k * NCPAD + j] = __uint_as_float(lo);
    }
    for (int idx = tid0; idx < 2 * H_ * H_; idx += stride) {
        int dir = idx / (H_ * H_);
        int rem = idx % (H_ * H_);
        int k = rem / H_, u = rem % H_;
        const float* Whh = dir ? Whh_b : Whh_f;
        float4 v;
        v.x = Whh[(size_t)(0 * H_ + u) * H_ + k];
        v.y = Whh[(size_t)(1 * H_ + u) * H_ + k];
        v.z = Whh[(size_t)(2 * H_ + u) * H_ + k];
        v.w = Whh[(size_t)(3 * H_ + u) * H_ + k];
        g_Wp[dir][k * H_ + u] = v;
    }
    for (int idx = tid0; idx < NCOLS; idx += stride) {
        int dir = idx / G4H, jj = idx % G4H;
        g_biasC[idx] = dir ? (bih_b[jj] + bhh_b[jj]) : (bih_f[jj] + bhh_f[jj]);
    }
}

// ---------------------------------------------------------------------------
// Prep: prefix-scan lens -> compacted row list; counting-sort spans by length.
// ---------------------------------------------------------------------------
__global__ void prep_kernel(const int* __restrict__ lens) {
    __shared__ int s[NSPAN];
    __shared__ int ll[NSPAN];
    __shared__ int cnt[T_ + 1];
    __shared__ int st[T_ + 1];
    int tid = threadIdx.x;
    int l = min(max(lens[tid], 0), T_);
    s[tid] = l;
    ll[tid] = l;
    if (tid <= T_) cnt[tid] = 0;
    __syncthreads();
    for (int d = 1; d < NSPAN; d <<= 1) {
        int v = (tid >= d) ? s[tid - d] : 0;
        __syncthreads();
        s[tid] += v;
        __syncthreads();
    }
    int off = s[tid] - l;
    for (int t = 0; t < l; t++) g_rows[off + t] = tid * T_ + t;
    if (tid == NSPAN - 1) g_cnt = s[tid];
    atomicAdd(&cnt[l], 1);
    __syncthreads();
    if (tid == 0) {
        int a = 0;
        for (int q = 0; q <= T_; q++) { st[q] = a; a += cnt[q]; }
    }
    __syncthreads();
    if (tid <= T_) {
        int pos = st[tid];
        for (int i = 0; i < NSPAN; i++)
            if (ll[i] == tid) g_order[pos++] = i;
    }
}

// ---------------------------------------------------------------------------
// Gather + split A once: compacted rows, each split to tf32 hi/lo in global.
// ---------------------------------------------------------------------------
__global__ void gather_split(const float* __restrict__ hidden,
                             const int*   __restrict__ starts) {
    int idx = blockIdx.x * blockDim.x + threadIdx.x;
    int total = g_cnt * (KDIM / 4);
    if (idx >= total) return;
    int m = idx / (KDIM / 4), q = idx % (KDIM / 4);
    int r = g_rows[m];
    int sp = r >> 5, t = r & 31;
    int b = sp >> 4, mm = sp & 15;
    int src = min(max(starts[b * MS_ + mm] + t, 0), S_ - 1);
    float4 v = *reinterpret_cast<const float4*>(&hidden[((size_t)b * S_ + src) * D_ + 4 * q]);
    float xs[4] = {v.x, v.y, v.z, v.w};
    float4 hi4, lo4;
    float* ph = &hi4.x; float* pl = &lo4.x;
#pragma unroll
    for (int j = 0; j < 4; j++) {
        unsigned hi, lo;
        tf32_split(xs[j], hi, lo);
        ph[j] = __uint_as_float(hi);
        pl[j] = __uint_as_float(lo);
    }
    *reinterpret_cast<float4*>(&g_Ahi[(size_t)m * KDIM + 4 * q]) = hi4;
    *reinterpret_cast<float4*>(&g_Alo[(size_t)m * KDIM + 4 * q]) = lo4;
}

// ---------------------------------------------------------------------------
// Pure-mma tf32 3-pass GEMM, cp.async double-buffered.
// Tile 128x128xKC, 8 warps (2x4), warp tile 64x32, mma m16n8k8.
// ---------------------------------------------------------------------------
#define MMA_TF32(d, a, b)                                                      \
    asm volatile("mma.sync.aligned.m16n8k8.row.col.f32.tf32.tf32.f32 "          \
                 "{%0,%1,%2,%3}, {%4,%5,%6,%7}, {%8,%9}, {%0,%1,%2,%3};"        \
                 : "+f"(d[0]), "+f"(d[1]), "+f"(d[2]), "+f"(d[3])               \
                 : "r"(a[0]), "r"(a[1]), "r"(a[2]), "r"(a[3]),                  \
                   "r"(b[0]), "r"(b[1]));

__device__ __forceinline__ void cp16(float* smem_ptr, const float* gptr) {
    unsigned saddr = (unsigned)__cvta_generic_to_shared(smem_ptr);
    asm volatile("cp.async.cg.shared.global [%0], [%1], 16;" :: "r"(saddr), "l"(gptr));
}

#define A_TILE (128 * APITCH)          // 4608 floats
#define B_TILE (KC * BPITCH)           // 4352 floats
#define STG    (2 * A_TILE + 2 * B_TILE) // 17920 floats per stage

extern __shared__ float smem_dyn[];

__global__ __launch_bounds__(256, 1) void gemm_tc(void) {
    const int cnt = g_cnt;
    const int m0  = blockIdx.y * 128;
    if (m0 >= cnt) return;
    const int n0  = blockIdx.x * 128;

    __shared__ int rowIdx[128];
    int tid = threadIdx.x;
    if (tid < 128) {
        int m = m0 + tid;
        rowIdx[tid] = (m < cnt) ? g_rows[m] : -1;
    }

    float acc[16][4];
#pragma unroll
    for (int i = 0; i < 16; i++)
#pragma unroll
        for (int q = 0; q < 4; q++) acc[i][q] = 0.f;

    int lane = tid & 31, wid = tid >> 5;
    int wm = wid >> 2, wn = wid & 3;
    int g = lane >> 2, tg = lane & 3;

    // stage loader
    auto load_stage = [&](int stage, int k0) {
        float* Ah = smem_dyn + stage * STG;
        float* Al = Ah + A_TILE;
        float* Bh = Ah + 2 * A_TILE;
        float* Bl = Bh + B_TILE;
#pragma unroll
        for (int i = 0; i < 4; i++) {
            int id = tid + i * 256;
            int m = id >> 3, c = id & 7;   // 128 rows x 8 chunks
            const float* gh = &g_Ahi[(size_t)(m0 + m) * KDIM + k0 + c * 4];
            const float* gl = &g_Alo[(size_t)(m0 + m) * KDIM + k0 + c * 4];
            cp16(&Ah[m * APITCH + c * 4], gh);
            cp16(&Al[m * APITCH + c * 4], gl);
        }
#pragma unroll
        for (int i = 0; i < 4; i++) {
            int id = tid + i * 256;
            int k = id >> 5, c = id & 31;  // 32 k x 32 chunks
            const float* gh = &g_Bhi[(size_t)(k0 + k) * NCPAD + n0 + c * 4];
            const float* gl = &g_Blo[(size_t)(k0 + k) * NCPAD + n0 + c * 4];
            cp16(&Bh[k * BPITCH + c * 4], gh);
            cp16(&Bl[k * BPITCH + c * 4], gl);
        }
    };

    const int NITER = KDIM / KC;   // 25
    load_stage(0, 0);
    asm volatile("cp.async.commit_group;");

    for (int it = 0; it < NITER; it++) {
        if (it + 1 < NITER) load_stage((it + 1) & 1, (it + 1) * KC);
        asm volatile("cp.async.commit_group;");
        asm volatile("cp.async.wait_group 1;");
        __syncthreads();

        const float* Ah = smem_dyn + (it & 1) * STG;
        const float* Al = Ah + A_TILE;
        const float* Bh = Ah + 2 * A_TILE;
        const float* Bl = Bh + B_TILE;

#pragma unroll
        for (int ks = 0; ks < 4; ks++) {
            int kk = ks * 8;
            unsigned ah[4][4], al[4][4];
#pragma unroll
            for (int mt = 0; mt < 4; mt++) {
                int r0 = wm * 64 + mt * 16 + g;
                const float* A0 = Ah + r0 * APITCH + kk + tg;
                const float* A1 = Al + r0 * APITCH + kk + tg;
                ah[mt][0] = __float_as_uint(A0[0]);
                ah[mt][1] = __float_as_uint(A0[8 * APITCH]);
                ah[mt][2] = __float_as_uint(A0[4]);
                ah[mt][3] = __float_as_uint(A0[8 * APITCH + 4]);
                al[mt][0] = __float_as_uint(A1[0]);
                al[mt][1] = __float_as_uint(A1[8 * APITCH]);
                al[mt][2] = __float_as_uint(A1[4]);
                al[mt][3] = __float_as_uint(A1[8 * APITCH + 4]);
            }
            unsigned bh[4][2], bl[4][2];
#pragma unroll
            for (int nt = 0; nt < 4; nt++) {
                int c = wn * 32 + nt * 8 + g;
                bh[nt][0] = __float_as_uint(Bh[(kk + tg) * BPITCH + c]);
                bh[nt][1] = __float_as_uint(Bh[(kk + tg + 4) * BPITCH + c]);
                bl[nt][0] = __float_as_uint(Bl[(kk + tg) * BPITCH + c]);
                bl[nt][1] = __float_as_uint(Bl[(kk + tg + 4) * BPITCH + c]);
            }
#pragma unroll
            for (int mt = 0; mt < 4; mt++)
#pragma unroll
                for (int nt = 0; nt < 4; nt++) {
                    MMA_TF32(acc[mt * 4 + nt], ah[mt], bh[nt]);
                    MMA_TF32(acc[mt * 4 + nt], ah[mt], bl[nt]);
                    MMA_TF32(acc[mt * 4 + nt], al[mt], bh[nt]);
                }
        }
        __syncthreads();
    }

    // epilogue: bias + scatter-store to Z at original row ids
#pragma unroll
    for (int mt = 0; mt < 4; mt++) {
        int lr0 = wm * 64 + mt * 16 + g;
#pragma unroll
        for (int nt = 0; nt < 4; nt++) {
            int c0 = n0 + wn * 32 + nt * 8 + tg * 2;
            float* a = acc[mt * 4 + nt];
#pragma unroll
            for (int q = 0; q < 4; q++) {
                int lr = lr0 + ((q >= 2) ? 8 : 0);
                int c  = c0 + (q & 1);
                if (m0 + lr < cnt && c < NCOLS) {
                    float v = a[q] + g_biasC[c];
                    int rid = rowIdx[lr];
                    if (c < G4H) g_Z[0][(size_t)rid * G4H + c]          = v;
                    else         g_Z[1][(size_t)rid * G4H + (c - G4H)] = v;
                }
            }
        }
    }
}

// ---------------------------------------------------------------------------
// Recurrence: thread u owns hidden unit u. Double-buffered h in smem
// (1 syncthreads/step), float4 k-vectorization, two length-paired groups
// per CTA so all 128 CTAs do ~uniform total steps on their own SM.
// ---------------------------------------------------------------------------
__device__ __forceinline__ float fast_sig(float x)  { return 1.f / (1.f + __expf(-x)); }
__device__ __forceinline__ float fast_tanh(float x) {
    float t = __expf(-2.f * x);
    return __fdividef(1.f - t, 1.f + t);
}

__global__ __launch_bounds__(224) void lstm_kernel(const int* __restrict__ span_lens) {
    __shared__ float4 h4[2][PSPAN][H_ / 4];
    __shared__ int    sp_sh[PSPAN];
    __shared__ int    len_sh[PSPAN];

    int tid = threadIdx.x;
    int dir = blockIdx.y;
    int u   = tid;
    bool act = u < H_;

    const float*  Zd = g_Z[dir];
    const float4* Wp = g_Wp[dir];

    for (int phase = 0; phase < 2; phase++) {
        int grp = phase ? (127 - (int)blockIdx.x) : (int)blockIdx.x;
        int n0  = grp * PSPAN;

        __syncthreads();  // smem reuse fence between phases
        if (tid < PSPAN) {
            int sp = g_order[n0 + tid];
            sp_sh[tid]  = sp;
            len_sh[tid] = min(max(span_lens[sp], 0), T_);
        }
        {   // zero buffer 0
            float* hz = (float*)h4;
            for (int i = tid; i < PSPAN * H_; i += 224) hz[i] = 0.f;
        }
        __syncthreads();

        int maxL = 0;
#pragma unroll
        for (int p = 0; p < PSPAN; p++) maxL = max(maxL, len_sh[p]);

        float c[PSPAN], feat[PSPAN], hreg[PSPAN];
#pragma unroll
        for (int p = 0; p < PSPAN; p++) { c[p] = 0.f; feat[p] = 0.f; hreg[p] = 0.f; }

        int buf = 0;
        for (int s = 0; s < maxL; s++) {
            float a0[PSPAN], a1[PSPAN], a2[PSPAN], a3[PSPAN];
            if (act) {
#pragma unroll
                for (int p = 0; p < PSPAN; p++) {
                    int L = len_sh[p];
                    int t = dir ? (L - 1 - s) : s;
                    if (s >= L) t = 0;
                    const float* z = Zd + ((size_t)sp_sh[p] * T_ + t) * G4H;
                    a0[p] = z[u];
                    a1[p] = z[H_ + u];
                    a2[p] = z[2 * H_ + u];
                    a3[p] = z[3 * H_ + u];
                }
#pragma unroll 2
                for (int k = 0; k < H_; k += 4) {
                    float4 w0 = Wp[(k + 0) * H_ + u];
                    float4 w1 = Wp[(k + 1) * H_ + u];
                    float4 w2 = Wp[(k + 2) * H_ + u];
                    float4 w3 = Wp[(k + 3) * H_ + u];
#pragma unroll
                    for (int p = 0; p < PSPAN; p++) {
                        float4 hv = h4[buf][p][k >> 2];
                        a0[p] += w0.x * hv.x; a0[p] += w1.x * hv.y;
                        a0[p] += w2.x * hv.z; a0[p] += w3.x * hv.w;
                        a1[p] += w0.y * hv.x; a1[p] += w1.y * hv.y;
                        a1[p] += w2.y * hv.z; a1[p] += w3.y * hv.w;
                        a2[p] += w0.z * hv.x; a2[p] += w1.z * hv.y;
                        a2[p] += w2.z * hv.z; a2[p] += w3.z * hv.w;
                        a3[p] += w0.w * hv.x; a3[p] += w1.w * hv.y;
                        a3[p] += w2.w * hv.z; a3[p] += w3.w * hv.w;
                    }
                }
#pragma unroll
                for (int p = 0; p < PSPAN; p++) {
                    if (s < len_sh[p]) {
                        float ig = fast_sig(a0[p]);
                        float fg = fast_sig(a1[p]);
                        float gg = fast_tanh(a2[p]);
                        float og = fast_sig(a3[p]);
                        float cn = fg * c[p] + ig * gg;
                        c[p] = cn;
                        hreg[p] = og * fast_tanh(cn);
                        feat[p] += hreg[p];
                    }
                    ((float*)&h4[buf ^ 1][p][0])[u] = hreg[p];
                }
            }
            __syncthreads();
            buf ^= 1;
        }

        if (act) {
#pragma unroll
            for (int p = 0; p < PSPAN; p++)
                g_feats[(size_t)sp_sh[p] * (2 * H_) + dir * H_ + u] = feat[p];
        }
    }
}

// ---------------------------------------------------------------------------
// logits: 16 spans x 12 slots per block
// ---------------------------------------------------------------------------
__global__ __launch_bounds__(192) void logits_kernel(const float* __restrict__ slot_embs,
                                                     const float* __restrict__ slot_mask,
                                                     float* __restrict__ out) {
    __shared__ float f_sm[16][2 * H_];
    __shared__ float se_sm[2 * H_ * NS_];

    int tid = threadIdx.x;
    int n0  = blockIdx.x * 16;

    for (int i = tid; i < 2 * H_ * NS_; i += blockDim.x) se_sm[i] = slot_embs[i];
    for (int i = tid; i < 16 * 2 * H_; i += blockDim.x) {
        int sp = i / (2 * H_), h = i % (2 * H_);
        f_sm[sp][h] = g_feats[(size_t)(n0 + sp) * (2 * H_) + h];
    }
    __syncthreads();

    int sp = tid / NS_, ns = tid % NS_;
    float acc = 0.f;
#pragma unroll 8
    for (int h = 0; h < 2 * H_; h++) acc += f_sm[sp][h] * se_sm[h * NS_ + ns];
    out[(n0 + sp) * NS_ + ns] = acc * slot_mask[n0 + sp];
}

// ---------------------------------------------------------------------------
extern "C" void kernel_launch(void* const* d_in, const int* in_sizes, int n_in,
                              void* d_out, int out_size) {
    const float* hidden    = (const float*)d_in[0];
    const float* Wih_f     = (const float*)d_in[1];
    const float* Whh_f     = (const float*)d_in[2];
    const float* bih_f     = (const float*)d_in[3];
    const float* bhh_f     = (const float*)d_in[4];
    const float* Wih_b     = (const float*)d_in[5];
    const float* Whh_b     = (const float*)d_in[6];
    const float* bih_b     = (const float*)d_in[7];
    const float* bhh_b     = (const float*)d_in[8];
    const float* slot_embs = (const float*)d_in[9];
    const int*   starts    = (const int*)d_in[10];
    const int*   lens      = (const int*)d_in[11];
    const float* slot_mask = (const float*)d_in[12];
    float* out = (float*)d_out;

    const int gemm_smem = 2 * STG * (int)sizeof(float);   // 143360 B
    cudaFuncSetAttribute(gemm_tc, cudaFuncAttributeMaxDynamicSharedMemorySize, gemm_smem);

    pack_kernel<<<1024, 256>>>(Wih_f, Whh_f, bih_f, bhh_f,
                               Wih_b, Whh_b, bih_b, bhh_b);
    prep_kernel<<<1, NSPAN>>>(lens);

    gather_split<<<(MROWS * (KDIM / 4) + 255) / 256, 256>>>(hidden, starts);

    dim3 ggrid((NCOLS + 127) / 128, MROWS / 128);   // 13 x 256
    gemm_tc<<<ggrid, 256, gemm_smem>>>();

    dim3 lgrid(64, 2);                              // paired sorted groups
    lstm_kernel<<<lgrid, 224>>>(lens);

    logits_kernel<<<NSPAN / 16, 192>>>(slot_embs, slot_mask, out);
}

// round 4
// speedup vs baseline: 3.4262x; 1.2698x over previous
#include <cuda_runtime.h>
#include <cuda_bf16.h>
#include <math.h>

#define B_    64
#define S_    1024
#define D_    800
#define MS_   16
#define T_    32
#define H_    200
#define NS_   12
#define NSPAN (B_*MS_)        // 1024
#define MROWS (NSPAN*T_)      // 32768
#define KDIM  D_              // 800
#define KP    832             // K padded to multiple of 64
#define KP2   (KP/2)          // 416 u32 pairs per row
#define G4H   (4*H_)          // 800
#define NCOLS 1600
#define NCPAD 1664
#define PSPAN 8
#define KC    64
#define KC2   (KC/2)          // 32 u32 per row per stage
#define PITCH 36              // smem pitch in u32: (4g+tg) distinct banks

// -------- scratch (static device arrays; no runtime alloc) ------------------
__device__ float    g_Z[2][(size_t)MROWS * G4H];
__device__ unsigned g_Ah[(size_t)MROWS * KP2];     // gathered A, bf16-hi pairs
__device__ unsigned g_Al[(size_t)MROWS * KP2];     // bf16-lo residual pairs
__device__ unsigned g_Bh[(size_t)NCPAD * KP2];     // W^T n-major, bf16-hi pairs
__device__ unsigned g_Bl[(size_t)NCPAD * KP2];
__device__ float4   g_Wp[2][H_ * H_];
__device__ float    g_biasC[NCOLS];
__device__ float    g_feats[(size_t)NSPAN * 2 * H_];
__device__ int      g_rows[MROWS];
__device__ int      g_order[NSPAN];
__device__ int      g_cnt;

__device__ __forceinline__ unsigned bf16_split2(float x0, float x1,
                                                unsigned& lo_out) {
    __nv_bfloat16 h0 = __float2bfloat16_rn(x0);
    __nv_bfloat16 h1 = __float2bfloat16_rn(x1);
    __nv_bfloat16 l0 = __float2bfloat16_rn(x0 - __bfloat162float(h0));
    __nv_bfloat16 l1 = __float2bfloat16_rn(x1 - __bfloat162float(h1));
    unsigned hi = ((unsigned)__bfloat16_as_ushort(h1) << 16) | __bfloat16_as_ushort(h0);
    lo_out      = ((unsigned)__bfloat16_as_ushort(l1) << 16) | __bfloat16_as_ushort(l0);
    return hi;
}

// ---------------------------------------------------------------------------
// Pack: B (transposed Wih, both dirs) -> n-major bf16 hi/lo pairs; gate-pack
// Whh; combine biases.
// ---------------------------------------------------------------------------
__global__ void pack_kernel(const float* __restrict__ Wih_f, const float* __restrict__ Whh_f,
                            const float* __restrict__ bih_f, const float* __restrict__ bhh_f,
                            const float* __restrict__ Wih_b, const float* __restrict__ Whh_b,
                            const float* __restrict__ bih_b, const float* __restrict__ bhh_b) {
    int stride = gridDim.x * blockDim.x;
    int tid0   = blockIdx.x * blockDim.x + threadIdx.x;

    // B pack: thread handles 8 k-values of one j (coalesced reads along k)
    for (int idx = tid0; idx < NCPAD * (KP / 8); idx += stride) {
        int j = idx / (KP / 8), q = idx % (KP / 8);
        int k0 = q * 8;
        float xs[8];
#pragma unroll
        for (int e = 0; e < 8; e++) {
            int k = k0 + e;
            float v = 0.f;
            if (j < NCOLS && k < KDIM)
                v = (j < G4H) ? Wih_f[(size_t)j * D_ + k]
                              : Wih_b[(size_t)(j - G4H) * D_ + k];
            xs[e] = v;
        }
        uint4 hi4, lo4;
        hi4.x = bf16_split2(xs[0], xs[1], lo4.x);
        hi4.y = bf16_split2(xs[2], xs[3], lo4.y);
        hi4.z = bf16_split2(xs[4], xs[5], lo4.z);
        hi4.w = bf16_split2(xs[6], xs[7], lo4.w);
        *reinterpret_cast<uint4*>(&g_Bh[(size_t)j * KP2 + q * 4]) = hi4;
        *reinterpret_cast<uint4*>(&g_Bl[(size_t)j * KP2 + q * 4]) = lo4;
    }
    for (int idx = tid0; idx < 2 * H_ * H_; idx += stride) {
        int dir = idx / (H_ * H_);
        int rem = idx % (H_ * H_);
        int k = rem / H_, u = rem % H_;
        const float* Whh = dir ? Whh_b : Whh_f;
        float4 v;
        v.x = Whh[(size_t)(0 * H_ + u) * H_ + k];
        v.y = Whh[(size_t)(1 * H_ + u) * H_ + k];
        v.z = Whh[(size_t)(2 * H_ + u) * H_ + k];
        v.w = Whh[(size_t)(3 * H_ + u) * H_ + k];
        g_Wp[dir][k * H_ + u] = v;
    }
    for (int idx = tid0; idx < NCOLS; idx += stride) {
        int dir = idx / G4H, jj = idx % G4H;
        g_biasC[idx] = dir ? (bih_b[jj] + bhh_b[jj]) : (bih_f[jj] + bhh_f[jj]);
    }
}

// ---------------------------------------------------------------------------
// Prep: prefix-scan lens -> compacted row list; counting-sort spans by length.
// ---------------------------------------------------------------------------
__global__ void prep_kernel(const int* __restrict__ lens) {
    __shared__ int s[NSPAN];
    __shared__ int ll[NSPAN];
    __shared__ int cnt[T_ + 1];
    __shared__ int st[T_ + 1];
    int tid = threadIdx.x;
    int l = min(max(lens[tid], 0), T_);
    s[tid] = l;
    ll[tid] = l;
    if (tid <= T_) cnt[tid] = 0;
    __syncthreads();
    for (int d = 1; d < NSPAN; d <<= 1) {
        int v = (tid >= d) ? s[tid - d] : 0;
        __syncthreads();
        s[tid] += v;
        __syncthreads();
    }
    int off = s[tid] - l;
    for (int t = 0; t < l; t++) g_rows[off + t] = tid * T_ + t;
    if (tid == NSPAN - 1) g_cnt = s[tid];
    atomicAdd(&cnt[l], 1);
    __syncthreads();
    if (tid == 0) {
        int a = 0;
        for (int q = 0; q <= T_; q++) { st[q] = a; a += cnt[q]; }
    }
    __syncthreads();
    if (tid <= T_) {
        int pos = st[tid];
        for (int i = 0; i < NSPAN; i++)
            if (ll[i] == tid) g_order[pos++] = i;
    }
}

// ---------------------------------------------------------------------------
// Gather + bf16-split A once (compacted rows, K padded with zeros).
// Thread handles 8 consecutive k of one row.
// ---------------------------------------------------------------------------
__global__ void gather_split(const float* __restrict__ hidden,
                             const int*   __restrict__ starts) {
    int idx = blockIdx.x * blockDim.x + threadIdx.x;
    int total = g_cnt * (KP / 8);
    if (idx >= total) return;
    int m = idx / (KP / 8), q = idx % (KP / 8);
    int k0 = q * 8;
    float xs[8];
    if (k0 < KDIM) {
        int r = g_rows[m];
        int sp = r >> 5, t = r & 31;
        int b = sp >> 4, mm = sp & 15;
        int src = min(max(starts[b * MS_ + mm] + t, 0), S_ - 1);
        const float* base = &hidden[((size_t)b * S_ + src) * D_ + k0];
        float4 v0 = *reinterpret_cast<const float4*>(base);
        float4 v1 = *reinterpret_cast<const float4*>(base + 4);
        xs[0] = v0.x; xs[1] = v0.y; xs[2] = v0.z; xs[3] = v0.w;
        xs[4] = v1.x; xs[5] = v1.y; xs[6] = v1.z; xs[7] = v1.w;
    } else {
#pragma unroll
        for (int e = 0; e < 8; e++) xs[e] = 0.f;
    }
    uint4 hi4, lo4;
    hi4.x = bf16_split2(xs[0], xs[1], lo4.x);
    hi4.y = bf16_split2(xs[2], xs[3], lo4.y);
    hi4.z = bf16_split2(xs[4], xs[5], lo4.z);
    hi4.w = bf16_split2(xs[6], xs[7], lo4.w);
    *reinterpret_cast<uint4*>(&g_Ah[(size_t)m * KP2 + q * 4]) = hi4;
    *reinterpret_cast<uint4*>(&g_Al[(size_t)m * KP2 + q * 4]) = lo4;
}

// ---------------------------------------------------------------------------
// bf16 3-pass GEMM (Ah*Bh + Ah*Bl + Al*Bh), cp.async double-buffered.
// Tile 128x128xKC(=64), 8 warps (2x4), warp tile 64x32, mma m16n8k16.
// ---------------------------------------------------------------------------
#define MMA_BF16(d, a, b)                                                       \
    asm volatile("mma.sync.aligned.m16n8k16.row.col.f32.bf16.bf16.f32 "         \
                 "{%0,%1,%2,%3}, {%4,%5,%6,%7}, {%8,%9}, {%0,%1,%2,%3};"        \
                 : "+f"(d[0]), "+f"(d[1]), "+f"(d[2]), "+f"(d[3])               \
                 : "r"(a[0]), "r"(a[1]), "r"(a[2]), "r"(a[3]),                  \
                   "r"(b[0]), "r"(b[1]));

__device__ __forceinline__ void cp16(unsigned* smem_ptr, const unsigned* gptr) {
    unsigned saddr = (unsigned)__cvta_generic_to_shared(smem_ptr);
    asm volatile("cp.async.cg.shared.global [%0], [%1], 16;" :: "r"(saddr), "l"(gptr));
}

#define MAT_TILE (128 * PITCH)               // 4608 u32 per matrix
#define STG      (4 * MAT_TILE)              // Ah, Al, Bh, Bl = 18432 u32/stage

extern __shared__ unsigned smem_u[];

__global__ __launch_bounds__(256, 1) void gemm_tc(void) {
    const int cnt = g_cnt;
    const int m0  = blockIdx.y * 128;
    if (m0 >= cnt) return;
    const int n0  = blockIdx.x * 128;

    __shared__ int rowIdx[128];
    int tid = threadIdx.x;
    if (tid < 128) {
        int m = m0 + tid;
        rowIdx[tid] = (m < cnt) ? g_rows[m] : -1;
    }

    float acc[16][4];
#pragma unroll
    for (int i = 0; i < 16; i++)
#pragma unroll
        for (int q = 0; q < 4; q++) acc[i][q] = 0.f;

    int lane = tid & 31, wid = tid >> 5;
    int wm = wid >> 2, wn = wid & 3;
    int g = lane >> 2, tg = lane & 3;

    auto load_stage = [&](int stage, int k0u) {   // k0u: u32 offset = k0/2
        unsigned* Ah = smem_u + stage * STG;
        unsigned* Al = Ah + MAT_TILE;
        unsigned* Bh = Ah + 2 * MAT_TILE;
        unsigned* Bl = Bh + MAT_TILE;
#pragma unroll
        for (int i = 0; i < 4; i++) {
            int id = tid + i * 256;
            int m = id >> 3, c = id & 7;          // 128 rows x 8 chunks of 4 u32
            size_t go = (size_t)(m0 + m) * KP2 + k0u + c * 4;
            cp16(&Ah[m * PITCH + c * 4], &g_Ah[go]);
            cp16(&Al[m * PITCH + c * 4], &g_Al[go]);
        }
#pragma unroll
        for (int i = 0; i < 4; i++) {
            int id = tid + i * 256;
            int n = id >> 3, c = id & 7;
            size_t go = (size_t)(n0 + n) * KP2 + k0u + c * 4;
            cp16(&Bh[n * PITCH + c * 4], &g_Bh[go]);
            cp16(&Bl[n * PITCH + c * 4], &g_Bl[go]);
        }
    };

    const int NITER = KP / KC;   // 13
    load_stage(0, 0);
    asm volatile("cp.async.commit_group;");

    for (int it = 0; it < NITER; it++) {
        if (it + 1 < NITER) load_stage((it + 1) & 1, (it + 1) * KC2);
        asm volatile("cp.async.commit_group;");
        asm volatile("cp.async.wait_group 1;");
        __syncthreads();

        const unsigned* Ah = smem_u + (it & 1) * STG;
        const unsigned* Al = Ah + MAT_TILE;
        const unsigned* Bh = Ah + 2 * MAT_TILE;
        const unsigned* Bl = Bh + MAT_TILE;

#pragma unroll
        for (int ks = 0; ks < 4; ks++) {          // 4 k-slices of 16
            int kp = ks * 8;                      // u32 offset of slice
            unsigned ah[4][4], al[4][4];
#pragma unroll
            for (int mt = 0; mt < 4; mt++) {
                int r0 = wm * 64 + mt * 16 + g;
                const unsigned* A0 = Ah + r0 * PITCH + kp + tg;
                const unsigned* A1 = Al + r0 * PITCH + kp + tg;
                ah[mt][0] = A0[0];
                ah[mt][1] = A0[8 * PITCH];
                ah[mt][2] = A0[4];
                ah[mt][3] = A0[8 * PITCH + 4];
                al[mt][0] = A1[0];
                al[mt][1] = A1[8 * PITCH];
                al[mt][2] = A1[4];
                al[mt][3] = A1[8 * PITCH + 4];
            }
            unsigned bh[4][2], bl[4][2];
#pragma unroll
            for (int nt = 0; nt < 4; nt++) {
                int c = wn * 32 + nt * 8 + g;
                const unsigned* B0 = Bh + c * PITCH + kp + tg;
                const unsigned* B1 = Bl + c * PITCH + kp + tg;
                bh[nt][0] = B0[0];
                bh[nt][1] = B0[4];
                bl[nt][0] = B1[0];
                bl[nt][1] = B1[4];
            }
#pragma unroll
            for (int mt = 0; mt < 4; mt++)
#pragma unroll
                for (int nt = 0; nt < 4; nt++) {
                    MMA_BF16(acc[mt * 4 + nt], ah[mt], bh[nt]);
                    MMA_BF16(acc[mt * 4 + nt], ah[mt], bl[nt]);
                    MMA_BF16(acc[mt * 4 + nt], al[mt], bh[nt]);
                }
        }
        __syncthreads();
    }

    // epilogue: bias + scatter-store to Z at original row ids
#pragma unroll
    for (int mt = 0; mt < 4; mt++) {
        int lr0 = wm * 64 + mt * 16 + g;
#pragma unroll
        for (int nt = 0; nt < 4; nt++) {
            int c0 = n0 + wn * 32 + nt * 8 + tg * 2;
            float* a = acc[mt * 4 + nt];
#pragma unroll
            for (int q = 0; q < 4; q++) {
                int lr = lr0 + ((q >= 2) ? 8 : 0);
                int c  = c0 + (q & 1);
                if (m0 + lr < cnt && c < NCOLS) {
                    float v = a[q] + g_biasC[c];
                    int rid = rowIdx[lr];
                    if (c < G4H) g_Z[0][(size_t)rid * G4H + c]          = v;
                    else         g_Z[1][(size_t)rid * G4H + (c - G4H)] = v;
                }
            }
        }
    }
}

// ---------------------------------------------------------------------------
// Recurrence (unchanged): double-buffered h, float4 k-vectorization,
// length-paired sorted groups, 1 sync/step.
// ---------------------------------------------------------------------------
__device__ __forceinline__ float fast_sig(float x)  { return 1.f / (1.f + __expf(-x)); }
__device__ __forceinline__ float fast_tanh(float x) {
    float t = __expf(-2.f * x);
    return __fdividef(1.f - t, 1.f + t);
}

__global__ __launch_bounds__(224) void lstm_kernel(const int* __restrict__ span_lens) {
    __shared__ float4 h4[2][PSPAN][H_ / 4];
    __shared__ int    sp_sh[PSPAN];
    __shared__ int    len_sh[PSPAN];

    int tid = threadIdx.x;
    int dir = blockIdx.y;
    int u   = tid;
    bool act = u < H_;

    const float*  Zd = g_Z[dir];
    const float4* Wp = g_Wp[dir];

    for (int phase = 0; phase < 2; phase++) {
        int grp = phase ? (127 - (int)blockIdx.x) : (int)blockIdx.x;
        int n0  = grp * PSPAN;

        __syncthreads();
        if (tid < PSPAN) {
            int sp = g_order[n0 + tid];
            sp_sh[tid]  = sp;
            len_sh[tid] = min(max(span_lens[sp], 0), T_);
        }
        {
            float* hz = (float*)h4;
            for (int i = tid; i < PSPAN * H_; i += 224) hz[i] = 0.f;
        }
        __syncthreads();

        int maxL = 0;
#pragma unroll
        for (int p = 0; p < PSPAN; p++) maxL = max(maxL, len_sh[p]);

        float c[PSPAN], feat[PSPAN], hreg[PSPAN];
#pragma unroll
        for (int p = 0; p < PSPAN; p++) { c[p] = 0.f; feat[p] = 0.f; hreg[p] = 0.f; }

        int buf = 0;
        for (int s = 0; s < maxL; s++) {
            float a0[PSPAN], a1[PSPAN], a2[PSPAN], a3[PSPAN];
            if (act) {
#pragma unroll
                for (int p = 0; p < PSPAN; p++) {
                    int L = len_sh[p];
                    int t = dir ? (L - 1 - s) : s;
                    if (s >= L) t = 0;
                    const float* z = Zd + ((size_t)sp_sh[p] * T_ + t) * G4H;
                    a0[p] = z[u];
                    a1[p] = z[H_ + u];
                    a2[p] = z[2 * H_ + u];
                    a3[p] = z[3 * H_ + u];
                }
#pragma unroll 2
                for (int k = 0; k < H_; k += 4) {
                    float4 w0 = Wp[(k + 0) * H_ + u];
                    float4 w1 = Wp[(k + 1) * H_ + u];
                    float4 w2 = Wp[(k + 2) * H_ + u];
                    float4 w3 = Wp[(k + 3) * H_ + u];
#pragma unroll
                    for (int p = 0; p < PSPAN; p++) {
                        float4 hv = h4[buf][p][k >> 2];
                        a0[p] += w0.x * hv.x; a0[p] += w1.x * hv.y;
                        a0[p] += w2.x * hv.z; a0[p] += w3.x * hv.w;
                        a1[p] += w0.y * hv.x; a1[p] += w1.y * hv.y;
                        a1[p] += w2.y * hv.z; a1[p] += w3.y * hv.w;
                        a2[p] += w0.z * hv.x; a2[p] += w1.z * hv.y;
                        a2[p] += w2.z * hv.z; a2[p] += w3.z * hv.w;
                        a3[p] += w0.w * hv.x; a3[p] += w1.w * hv.y;
                        a3[p] += w2.w * hv.z; a3[p] += w3.w * hv.w;
                    }
                }
#pragma unroll
                for (int p = 0; p < PSPAN; p++) {
                    if (s < len_sh[p]) {
                        float ig = fast_sig(a0[p]);
                        float fg = fast_sig(a1[p]);
                        float gg = fast_tanh(a2[p]);
                        float og = fast_sig(a3[p]);
                        float cn = fg * c[p] + ig * gg;
                        c[p] = cn;
                        hreg[p] = og * fast_tanh(cn);
                        feat[p] += hreg[p];
                    }
                    ((float*)&h4[buf ^ 1][p][0])[u] = hreg[p];
                }
            }
            __syncthreads();
            buf ^= 1;
        }

        if (act) {
#pragma unroll
            for (int p = 0; p < PSPAN; p++)
                g_feats[(size_t)sp_sh[p] * (2 * H_) + dir * H_ + u] = feat[p];
        }
    }
}

// ---------------------------------------------------------------------------
// logits
// ---------------------------------------------------------------------------
__global__ __launch_bounds__(192) void logits_kernel(const float* __restrict__ slot_embs,
                                                     const float* __restrict__ slot_mask,
                                                     float* __restrict__ out) {
    __shared__ float f_sm[16][2 * H_];
    __shared__ float se_sm[2 * H_ * NS_];

    int tid = threadIdx.x;
    int n0  = blockIdx.x * 16;

    for (int i = tid; i < 2 * H_ * NS_; i += blockDim.x) se_sm[i] = slot_embs[i];
    for (int i = tid; i < 16 * 2 * H_; i += blockDim.x) {
        int sp = i / (2 * H_), h = i % (2 * H_);
        f_sm[sp][h] = g_feats[(size_t)(n0 + sp) * (2 * H_) + h];
    }
    __syncthreads();

    int sp = tid / NS_, ns = tid % NS_;
    float acc = 0.f;
#pragma unroll 8
    for (int h = 0; h < 2 * H_; h++) acc += f_sm[sp][h] * se_sm[h * NS_ + ns];
    out[(n0 + sp) * NS_ + ns] = acc * slot_mask[n0 + sp];
}

// ---------------------------------------------------------------------------
extern "C" void kernel_launch(void* const* d_in, const int* in_sizes, int n_in,
                              void* d_out, int out_size) {
    const float* hidden    = (const float*)d_in[0];
    const float* Wih_f     = (const float*)d_in[1];
    const float* Whh_f     = (const float*)d_in[2];
    const float* bih_f     = (const float*)d_in[3];
    const float* bhh_f     = (const float*)d_in[4];
    const float* Wih_b     = (const float*)d_in[5];
    const float* Whh_b     = (const float*)d_in[6];
    const float* bih_b     = (const float*)d_in[7];
    const float* bhh_b     = (const float*)d_in[8];
    const float* slot_embs = (const float*)d_in[9];
    const int*   starts    = (const int*)d_in[10];
    const int*   lens      = (const int*)d_in[11];
    const float* slot_mask = (const float*)d_in[12];
    float* out = (float*)d_out;

    const int gemm_smem = 2 * STG * (int)sizeof(unsigned);   // 147456 B
    cudaFuncSetAttribute(gemm_tc, cudaFuncAttributeMaxDynamicSharedMemorySize, gemm_smem);

    pack_kernel<<<1024, 256>>>(Wih_f, Whh_f, bih_f, bhh_f,
                               Wih_b, Whh_b, bih_b, bhh_b);
    prep_kernel<<<1, NSPAN>>>(lens);

    gather_split<<<(MROWS * (KP / 8) + 255) / 256, 256>>>(hidden, starts);

    dim3 ggrid(NCPAD / 128, MROWS / 128);   // 13 x 256 (tiles past count exit)
    gemm_tc<<<ggrid, 256, gemm_smem>>>();

    dim3 lgrid(64, 2);
    lstm_kernel<<<lgrid, 224>>>(lens);

    logits_kernel<<<NSPAN / 16, 192>>>(slot_embs, slot_mask, out);
}

// round 5
// speedup vs baseline: 4.5373x; 1.3243x over previous
#include <cuda_runtime.h>
#include <cuda_fp16.h>
#include <math.h>

#define B_    64
#define S_    1024
#define D_    800
#define MS_   16
#define T_    32
#define H_    200
#define NS_   12
#define NSPAN (B_*MS_)        // 1024
#define MROWS (NSPAN*T_)      // 32768
#define KDIM  D_              // 800
#define KP    832             // K padded to multiple of 64
#define KP2   (KP/2)          // 416 u32 (fp16 pairs) per row
#define G4H   (4*H_)          // 800
#define NCOLS 1600
#define NCPAD 1664
#define PSPAN 8
#define KC    64
#define KC2   (KC/2)          // 32 u32 per row per stage
#define PITCH 36              // smem pitch in u32: (4g+tg)%32 distinct banks

// -------- scratch (static device arrays; no runtime alloc) ------------------
__device__ float    g_Z[2][(size_t)MROWS * G4H];
__device__ unsigned g_A16[(size_t)MROWS * KP2];    // gathered A, fp16 pairs
__device__ unsigned g_B16[(size_t)NCPAD * KP2];    // W^T n-major, fp16 pairs
__device__ float4   g_Wp[2][H_ * H_];
__device__ float    g_biasC[NCPAD];
__device__ float    g_feats[(size_t)NSPAN * 2 * H_];
__device__ int      g_rows[MROWS];
__device__ int      g_order[NSPAN];
__device__ int      g_cnt;

__device__ __forceinline__ unsigned pack_h2(float x0, float x1) {
    __half2 h = __floats2half2_rn(x0, x1);
    return *reinterpret_cast<unsigned*>(&h);
}

// ---------------------------------------------------------------------------
// Pack: B (transposed Wih, both dirs) -> n-major fp16 pairs; gate-pack Whh;
// combine biases.
// ---------------------------------------------------------------------------
__global__ void pack_kernel(const float* __restrict__ Wih_f, const float* __restrict__ Whh_f,
                            const float* __restrict__ bih_f, const float* __restrict__ bhh_f,
                            const float* __restrict__ Wih_b, const float* __restrict__ Whh_b,
                            const float* __restrict__ bih_b, const float* __restrict__ bhh_b) {
    int stride = gridDim.x * blockDim.x;
    int tid0   = blockIdx.x * blockDim.x + threadIdx.x;

    for (int idx = tid0; idx < NCPAD * (KP / 8); idx += stride) {
        int j = idx / (KP / 8), q = idx % (KP / 8);
        int k0 = q * 8;
        float xs[8];
#pragma unroll
        for (int e = 0; e < 8; e++) {
            int k = k0 + e;
            float v = 0.f;
            if (j < NCOLS && k < KDIM)
                v = (j < G4H) ? Wih_f[(size_t)j * D_ + k]
                              : Wih_b[(size_t)(j - G4H) * D_ + k];
            xs[e] = v;
        }
        uint4 h4;
        h4.x = pack_h2(xs[0], xs[1]);
        h4.y = pack_h2(xs[2], xs[3]);
        h4.z = pack_h2(xs[4], xs[5]);
        h4.w = pack_h2(xs[6], xs[7]);
        *reinterpret_cast<uint4*>(&g_B16[(size_t)j * KP2 + q * 4]) = h4;
    }
    for (int idx = tid0; idx < 2 * H_ * H_; idx += stride) {
        int dir = idx / (H_ * H_);
        int rem = idx % (H_ * H_);
        int k = rem / H_, u = rem % H_;
        const float* Whh = dir ? Whh_b : Whh_f;
        float4 v;
        v.x = Whh[(size_t)(0 * H_ + u) * H_ + k];
        v.y = Whh[(size_t)(1 * H_ + u) * H_ + k];
        v.z = Whh[(size_t)(2 * H_ + u) * H_ + k];
        v.w = Whh[(size_t)(3 * H_ + u) * H_ + k];
        g_Wp[dir][k * H_ + u] = v;
    }
    for (int idx = tid0; idx < NCPAD; idx += stride) {
        float v = 0.f;
        if (idx < NCOLS) {
            int dir = idx / G4H, jj = idx % G4H;
            v = dir ? (bih_b[jj] + bhh_b[jj]) : (bih_f[jj] + bhh_f[jj]);
        }
        g_biasC[idx] = v;
    }
}

// ---------------------------------------------------------------------------
// Prep: prefix-scan lens -> compacted row list; counting-sort spans by length.
// ---------------------------------------------------------------------------
__global__ void prep_kernel(const int* __restrict__ lens) {
    __shared__ int s[NSPAN];
    __shared__ int ll[NSPAN];
    __shared__ int cnt[T_ + 1];
    __shared__ int st[T_ + 1];
    int tid = threadIdx.x;
    int l = min(max(lens[tid], 0), T_);
    s[tid] = l;
    ll[tid] = l;
    if (tid <= T_) cnt[tid] = 0;
    __syncthreads();
    for (int d = 1; d < NSPAN; d <<= 1) {
        int v = (tid >= d) ? s[tid - d] : 0;
        __syncthreads();
        s[tid] += v;
        __syncthreads();
    }
    int off = s[tid] - l;
    for (int t = 0; t < l; t++) g_rows[off + t] = tid * T_ + t;
    if (tid == NSPAN - 1) g_cnt = s[tid];
    atomicAdd(&cnt[l], 1);
    __syncthreads();
    if (tid == 0) {
        int a = 0;
        for (int q = 0; q <= T_; q++) { st[q] = a; a += cnt[q]; }
    }
    __syncthreads();
    if (tid <= T_) {
        int pos = st[tid];
        for (int i = 0; i < NSPAN; i++)
            if (ll[i] == tid) g_order[pos++] = i;
    }
}

// ---------------------------------------------------------------------------
// Gather A once -> fp16 pairs (compacted rows, K zero-padded).
// ---------------------------------------------------------------------------
__global__ void gather_split(const float* __restrict__ hidden,
                             const int*   __restrict__ starts) {
    int idx = blockIdx.x * blockDim.x + threadIdx.x;
    int total = g_cnt * (KP / 8);
    if (idx >= total) return;
    int m = idx / (KP / 8), q = idx % (KP / 8);
    int k0 = q * 8;
    float xs[8];
    if (k0 < KDIM) {
        int r = g_rows[m];
        int sp = r >> 5, t = r & 31;
        int b = sp >> 4, mm = sp & 15;
        int src = min(max(starts[b * MS_ + mm] + t, 0), S_ - 1);
        const float* base = &hidden[((size_t)b * S_ + src) * D_ + k0];
        float4 v0 = *reinterpret_cast<const float4*>(base);
        float4 v1 = *reinterpret_cast<const float4*>(base + 4);
        xs[0] = v0.x; xs[1] = v0.y; xs[2] = v0.z; xs[3] = v0.w;
        xs[4] = v1.x; xs[5] = v1.y; xs[6] = v1.z; xs[7] = v1.w;
    } else {
#pragma unroll
        for (int e = 0; e < 8; e++) xs[e] = 0.f;
    }
    uint4 h4;
    h4.x = pack_h2(xs[0], xs[1]);
    h4.y = pack_h2(xs[2], xs[3]);
    h4.z = pack_h2(xs[4], xs[5]);
    h4.w = pack_h2(xs[6], xs[7]);
    *reinterpret_cast<uint4*>(&g_A16[(size_t)m * KP2 + q * 4]) = h4;
}

// ---------------------------------------------------------------------------
// fp16 single-pass GEMM, cp.async double-buffered, 2 CTAs/SM.
// Tile 128x128xKC(=64), 8 warps (2x4), warp tile 64x32, mma m16n8k16.
// ---------------------------------------------------------------------------
#define MMA_FP16(d, a, b)                                                       \
    asm volatile("mma.sync.aligned.m16n8k16.row.col.f32.f16.f16.f32 "           \
                 "{%0,%1,%2,%3}, {%4,%5,%6,%7}, {%8,%9}, {%0,%1,%2,%3};"        \
                 : "+f"(d[0]), "+f"(d[1]), "+f"(d[2]), "+f"(d[3])               \
                 : "r"(a[0]), "r"(a[1]), "r"(a[2]), "r"(a[3]),                  \
                   "r"(b[0]), "r"(b[1]));

__device__ __forceinline__ void cp16(unsigned* smem_ptr, const unsigned* gptr) {
    unsigned saddr = (unsigned)__cvta_generic_to_shared(smem_ptr);
    asm volatile("cp.async.cg.shared.global [%0], [%1], 16;" :: "r"(saddr), "l"(gptr));
}

#define MAT_TILE (128 * PITCH)          // 4608 u32 per matrix
#define STG      (2 * MAT_TILE)         // A + B = 9216 u32/stage (36 KB)

extern __shared__ unsigned smem_u[];

__global__ __launch_bounds__(256, 2) void gemm_tc(void) {
    const int cnt = g_cnt;
    const int m0  = blockIdx.y * 128;
    if (m0 >= cnt) return;
    const int n0  = blockIdx.x * 128;

    __shared__ int rowIdx[128];
    int tid = threadIdx.x;
    if (tid < 128) {
        int m = m0 + tid;
        rowIdx[tid] = (m < cnt) ? g_rows[m] : -1;
    }

    float acc[16][4];
#pragma unroll
    for (int i = 0; i < 16; i++)
#pragma unroll
        for (int q = 0; q < 4; q++) acc[i][q] = 0.f;

    int lane = tid & 31, wid = tid >> 5;
    int wm = wid >> 2, wn = wid & 3;
    int g = lane >> 2, tg = lane & 3;

    auto load_stage = [&](int stage, int k0u) {
        unsigned* As = smem_u + stage * STG;
        unsigned* Bs = As + MAT_TILE;
#pragma unroll
        for (int i = 0; i < 4; i++) {
            int id = tid + i * 256;
            int m = id >> 3, c = id & 7;          // 128 rows x 8 chunks of 4 u32
            cp16(&As[m * PITCH + c * 4], &g_A16[(size_t)(m0 + m) * KP2 + k0u + c * 4]);
        }
#pragma unroll
        for (int i = 0; i < 4; i++) {
            int id = tid + i * 256;
            int n = id >> 3, c = id & 7;
            cp16(&Bs[n * PITCH + c * 4], &g_B16[(size_t)(n0 + n) * KP2 + k0u + c * 4]);
        }
    };

    const int NITER = KP / KC;   // 13
    load_stage(0, 0);
    asm volatile("cp.async.commit_group;");

    for (int it = 0; it < NITER; it++) {
        if (it + 1 < NITER) load_stage((it + 1) & 1, (it + 1) * KC2);
        asm volatile("cp.async.commit_group;");
        asm volatile("cp.async.wait_group 1;");
        __syncthreads();

        const unsigned* As = smem_u + (it & 1) * STG;
        const unsigned* Bs = As + MAT_TILE;

#pragma unroll
        for (int ks = 0; ks < 4; ks++) {          // 4 k-slices of 16
            int kp = ks * 8;
            unsigned af[4][4];
#pragma unroll
            for (int mt = 0; mt < 4; mt++) {
                int r0 = wm * 64 + mt * 16 + g;
                const unsigned* A0 = As + r0 * PITCH + kp + tg;
                af[mt][0] = A0[0];
                af[mt][1] = A0[8 * PITCH];
                af[mt][2] = A0[4];
                af[mt][3] = A0[8 * PITCH + 4];
            }
            unsigned bf[4][2];
#pragma unroll
            for (int nt = 0; nt < 4; nt++) {
                int c = wn * 32 + nt * 8 + g;
                const unsigned* B0 = Bs + c * PITCH + kp + tg;
                bf[nt][0] = B0[0];
                bf[nt][1] = B0[4];
            }
#pragma unroll
            for (int mt = 0; mt < 4; mt++)
#pragma unroll
                for (int nt = 0; nt < 4; nt++)
                    MMA_FP16(acc[mt * 4 + nt], af[mt], bf[nt]);
        }
        __syncthreads();
    }

    // epilogue: bias + float2 scatter-store to Z at original row ids
#pragma unroll
    for (int mt = 0; mt < 4; mt++) {
        int lr0 = wm * 64 + mt * 16 + g;
#pragma unroll
        for (int nt = 0; nt < 4; nt++) {
            int c = n0 + wn * 32 + nt * 8 + tg * 2;
            if (c >= NCOLS) continue;
            float* a = acc[mt * 4 + nt];
            float2 bias = *reinterpret_cast<const float2*>(&g_biasC[c]);
            int dirb = (c >= G4H);
            int cc   = dirb ? (c - G4H) : c;
#pragma unroll
            for (int h = 0; h < 2; h++) {
                int lr = lr0 + h * 8;
                if (m0 + lr < cnt) {
                    float2 v;
                    v.x = a[h * 2 + 0] + bias.x;
                    v.y = a[h * 2 + 1] + bias.y;
                    int rid = rowIdx[lr];
                    *reinterpret_cast<float2*>(&g_Z[dirb][(size_t)rid * G4H + cc]) = v;
                }
            }
        }
    }
}

// ---------------------------------------------------------------------------
// Recurrence (unchanged): double-buffered h, float4 k-vectorization,
// length-paired sorted groups, 1 sync/step.
// ---------------------------------------------------------------------------
__device__ __forceinline__ float fast_sig(float x)  { return 1.f / (1.f + __expf(-x)); }
__device__ __forceinline__ float fast_tanh(float x) {
    float t = __expf(-2.f * x);
    return __fdividef(1.f - t, 1.f + t);
}

__global__ __launch_bounds__(224) void lstm_kernel(const int* __restrict__ span_lens) {
    __shared__ float4 h4[2][PSPAN][H_ / 4];
    __shared__ int    sp_sh[PSPAN];
    __shared__ int    len_sh[PSPAN];

    int tid = threadIdx.x;
    int dir = blockIdx.y;
    int u   = tid;
    bool act = u < H_;

    const float*  Zd = g_Z[dir];
    const float4* Wp = g_Wp[dir];

    for (int phase = 0; phase < 2; phase++) {
        int grp = phase ? (127 - (int)blockIdx.x) : (int)blockIdx.x;
        int n0  = grp * PSPAN;

        __syncthreads();
        if (tid < PSPAN) {
            int sp = g_order[n0 + tid];
            sp_sh[tid]  = sp;
            len_sh[tid] = min(max(span_lens[sp], 0), T_);
        }
        {
            float* hz = (float*)h4;
            for (int i = tid; i < PSPAN * H_; i += 224) hz[i] = 0.f;
        }
        __syncthreads();

        int maxL = 0;
#pragma unroll
        for (int p = 0; p < PSPAN; p++) maxL = max(maxL, len_sh[p]);

        float c[PSPAN], feat[PSPAN], hreg[PSPAN];
#pragma unroll
        for (int p = 0; p < PSPAN; p++) { c[p] = 0.f; feat[p] = 0.f; hreg[p] = 0.f; }

        int buf = 0;
        for (int s = 0; s < maxL; s++) {
            float a0[PSPAN], a1[PSPAN], a2[PSPAN], a3[PSPAN];
            if (act) {
#pragma unroll
                for (int p = 0; p < PSPAN; p++) {
                    int L = len_sh[p];
                    int t = dir ? (L - 1 - s) : s;
                    if (s >= L) t = 0;
                    const float* z = Zd + ((size_t)sp_sh[p] * T_ + t) * G4H;
                    a0[p] = z[u];
                    a1[p] = z[H_ + u];
                    a2[p] = z[2 * H_ + u];
                    a3[p] = z[3 * H_ + u];
                }
#pragma unroll 2
                for (int k = 0; k < H_; k += 4) {
                    float4 w0 = Wp[(k + 0) * H_ + u];
                    float4 w1 = Wp[(k + 1) * H_ + u];
                    float4 w2 = Wp[(k + 2) * H_ + u];
                    float4 w3 = Wp[(k + 3) * H_ + u];
#pragma unroll
                    for (int p = 0; p < PSPAN; p++) {
                        float4 hv = h4[buf][p][k >> 2];
                        a0[p] += w0.x * hv.x; a0[p] += w1.x * hv.y;
                        a0[p] += w2.x * hv.z; a0[p] += w3.x * hv.w;
                        a1[p] += w0.y * hv.x; a1[p] += w1.y * hv.y;
                        a1[p] += w2.y * hv.z; a1[p] += w3.y * hv.w;
                        a2[p] += w0.z * hv.x; a2[p] += w1.z * hv.y;
                        a2[p] += w2.z * hv.z; a2[p] += w3.z * hv.w;
                        a3[p] += w0.w * hv.x; a3[p] += w1.w * hv.y;
                        a3[p] += w2.w * hv.z; a3[p] += w3.w * hv.w;
                    }
                }
#pragma unroll
                for (int p = 0; p < PSPAN; p++) {
                    if (s < len_sh[p]) {
                        float ig = fast_sig(a0[p]);
                        float fg = fast_sig(a1[p]);
                        float gg = fast_tanh(a2[p]);
                        float og = fast_sig(a3[p]);
                        float cn = fg * c[p] + ig * gg;
                        c[p] = cn;
                        hreg[p] = og * fast_tanh(cn);
                        feat[p] += hreg[p];
                    }
                    ((float*)&h4[buf ^ 1][p][0])[u] = hreg[p];
                }
            }
            __syncthreads();
            buf ^= 1;
        }

        if (act) {
#pragma unroll
            for (int p = 0; p < PSPAN; p++)
                g_feats[(size_t)sp_sh[p] * (2 * H_) + dir * H_ + u] = feat[p];
        }
    }
}

// ---------------------------------------------------------------------------
// logits
// ---------------------------------------------------------------------------
__global__ __launch_bounds__(192) void logits_kernel(const float* __restrict__ slot_embs,
                                                     const float* __restrict__ slot_mask,
                                                     float* __restrict__ out) {
    __shared__ float f_sm[16][2 * H_];
    __shared__ float se_sm[2 * H_ * NS_];

    int tid = threadIdx.x;
    int n0  = blockIdx.x * 16;

    for (int i = tid; i < 2 * H_ * NS_; i += blockDim.x) se_sm[i] = slot_embs[i];
    for (int i = tid; i < 16 * 2 * H_; i += blockDim.x) {
        int sp = i / (2 * H_), h = i % (2 * H_);
        f_sm[sp][h] = g_feats[(size_t)(n0 + sp) * (2 * H_) + h];
    }
    __syncthreads();

    int sp = tid / NS_, ns = tid % NS_;
    float acc = 0.f;
#pragma unroll 8
    for (int h = 0; h < 2 * H_; h++) acc += f_sm[sp][h] * se_sm[h * NS_ + ns];
    out[(n0 + sp) * NS_ + ns] = acc * slot_mask[n0 + sp];
}

// ---------------------------------------------------------------------------
extern "C" void kernel_launch(void* const* d_in, const int* in_sizes, int n_in,
                              void* d_out, int out_size) {
    const float* hidden    = (const float*)d_in[0];
    const float* Wih_f     = (const float*)d_in[1];
    const float* Whh_f     = (const float*)d_in[2];
    const float* bih_f     = (const float*)d_in[3];
    const float* bhh_f     = (const float*)d_in[4];
    const float* Wih_b     = (const float*)d_in[5];
    const float* Whh_b     = (const float*)d_in[6];
    const float* bih_b     = (const float*)d_in[7];
    const float* bhh_b     = (const float*)d_in[8];
    const float* slot_embs = (const float*)d_in[9];
    const int*   starts    = (const int*)d_in[10];
    const int*   lens      = (const int*)d_in[11];
    const float* slot_mask = (const float*)d_in[12];
    float* out = (float*)d_out;

    const int gemm_smem = 2 * STG * (int)sizeof(unsigned);   // 73728 B
    cudaFuncSetAttribute(gemm_tc, cudaFuncAttributeMaxDynamicSharedMemorySize, gemm_smem);

    pack_kernel<<<1024, 256>>>(Wih_f, Whh_f, bih_f, bhh_f,
                               Wih_b, Whh_b, bih_b, bhh_b);
    prep_kernel<<<1, NSPAN>>>(lens);

    gather_split<<<(MROWS * (KP / 8) + 255) / 256, 256>>>(hidden, starts);

    dim3 ggrid(NCPAD / 128, MROWS / 128);   // 13 x 256 (tiles past count exit)
    gemm_tc<<<ggrid, 256, gemm_smem>>>();

    dim3 lgrid(64, 2);
    lstm_kernel<<<lgrid, 224>>>(lens);

    logits_kernel<<<NSPAN / 16, 192>>>(slot_embs, slot_mask, out);
}